// round 1
// baseline (speedup 1.0000x reference)
#include <cuda_runtime.h>
#include <cstdint>

#define DIN     4096
#define RANK    64
#define NADAPT  8
#define NBATCH  4
#define MTOT    8192      // B*S
#define NR      512       // NADAPT*RANK per component
#define HCOLS   1536      // 3*NR
#define DOUT    4096
#define OUTCOLS 12288     // 3*DOUT

// 50 MB scratch for the rank-space intermediate H = (X @ A_cat) * coef
__device__ float g_H[(size_t)MTOT * HCOLS];

__device__ __forceinline__ unsigned f2tf32(float f) {
    unsigned u;
    asm("cvt.rna.tf32.f32 %0, %1;" : "=r"(u) : "f"(f));
    return u;
}

__device__ __forceinline__ void mma_tf32(float* c, const unsigned* a, const unsigned* b) {
    asm volatile(
        "mma.sync.aligned.m16n8k8.row.col.f32.tf32.tf32.f32 "
        "{%0,%1,%2,%3}, {%4,%5,%6,%7}, {%8,%9}, {%0,%1,%2,%3};\n"
        : "+f"(c[0]), "+f"(c[1]), "+f"(c[2]), "+f"(c[3])
        : "r"(a[0]), "r"(a[1]), "r"(a[2]), "r"(a[3]), "r"(b[0]), "r"(b[1]));
}

// ---------------------------------------------------------------------------
// GEMM1: H[8192,1536] = X[8192,4096] @ A_cat[4096,1536], epilogue *= coef
// Block tile 128x64 (BN=64 => single (comp,n) per block; BM=128 => single b)
// ---------------------------------------------------------------------------
constexpr int BK  = 32;
constexpr int BM  = 128;
constexpr int BN1 = 64;
constexpr int XS  = 36;   // Xs row stride: banks (4*row + k) % 32 -> conflict-free frags
constexpr int AS1 = 72;   // As row stride: 72 % 32 == 8 -> banks (8k + j) conflict-free

__global__ void __launch_bounds__(256, 2)
lora_gemm1(const float* __restrict__ x,
           const float* __restrict__ qA,
           const float* __restrict__ kA,
           const float* __restrict__ vA,
           const float* __restrict__ masks,
           const float* __restrict__ scaling)
{
    __shared__ unsigned Xs[BM][XS];   // [row][k]  (tf32 bit patterns)
    __shared__ unsigned As[BK][AS1];  // [k][col]

    const int tid  = threadIdx.x;
    const int lane = tid & 31;
    const int wid  = tid >> 5;
    const int wm   = wid & 3;   // 4 warps over M (32 rows each)
    const int wn   = wid >> 2;  // 2 warps over N (32 cols each)
    const int lr   = lane >> 2; // groupID
    const int lc   = lane & 3;  // threadID in group

    const int row0 = blockIdx.x * BM;
    const int col0 = blockIdx.y * BN1;
    const int comp = col0 >> 9;          // 0=q,1=k,2=v
    const int n    = (col0 & 511) >> 6;  // adapter index
    const int b    = row0 >> 11;         // batch index (2048 rows/batch)
    const float coef = scaling[n] * masks[n * NBATCH + b];
    const float* A  = (comp == 0) ? qA : ((comp == 1) ? kA : vA);
    const float* Ab = A + (size_t)n * DIN * RANK;   // [i][r], r contiguous

    float acc[2][4][4];
    #pragma unroll
    for (int i = 0; i < 2; i++)
        #pragma unroll
        for (int j = 0; j < 4; j++)
            #pragma unroll
            for (int q = 0; q < 4; q++) acc[i][j][q] = 0.f;

    const float* xbase = x + (size_t)row0 * DIN;

    float4 xr[4], ar[2];
    // stage tile 0
    #pragma unroll
    for (int i = 0; i < 4; i++) {
        int lin = tid + 256 * i;
        xr[i] = *(const float4*)(xbase + (size_t)(lin >> 3) * DIN + ((lin & 7) << 2));
    }
    #pragma unroll
    for (int i = 0; i < 2; i++) {
        int lin = tid + 256 * i;
        ar[i] = *(const float4*)(Ab + (size_t)(lin >> 4) * RANK + ((lin & 15) << 2));
    }

    const int NT = DIN / BK;  // 128
    for (int t = 0; t < NT; t++) {
        // commit staged tile to smem (with tf32 rounding)
        #pragma unroll
        for (int i = 0; i < 4; i++) {
            int lin = tid + 256 * i;
            int r = lin >> 3, c = (lin & 7) << 2;
            Xs[r][c + 0] = f2tf32(xr[i].x);
            Xs[r][c + 1] = f2tf32(xr[i].y);
            Xs[r][c + 2] = f2tf32(xr[i].z);
            Xs[r][c + 3] = f2tf32(xr[i].w);
        }
        #pragma unroll
        for (int i = 0; i < 2; i++) {
            int lin = tid + 256 * i;
            int k = lin >> 4, c = (lin & 15) << 2;
            As[k][c + 0] = f2tf32(ar[i].x);
            As[k][c + 1] = f2tf32(ar[i].y);
            As[k][c + 2] = f2tf32(ar[i].z);
            As[k][c + 3] = f2tf32(ar[i].w);
        }
        __syncthreads();

        // prefetch next tile into registers while computing
        if (t + 1 < NT) {
            int kt = (t + 1) * BK;
            #pragma unroll
            for (int i = 0; i < 4; i++) {
                int lin = tid + 256 * i;
                xr[i] = *(const float4*)(xbase + (size_t)(lin >> 3) * DIN + kt + ((lin & 7) << 2));
            }
            #pragma unroll
            for (int i = 0; i < 2; i++) {
                int lin = tid + 256 * i;
                ar[i] = *(const float4*)(Ab + (size_t)(kt + (lin >> 4)) * RANK + ((lin & 15) << 2));
            }
        }

        #pragma unroll
        for (int ks = 0; ks < 4; ks++) {
            const int k8 = ks * 8;
            unsigned af[2][4], bf[4][2];
            #pragma unroll
            for (int mm = 0; mm < 2; mm++) {
                int r = wm * 32 + mm * 16 + lr;
                af[mm][0] = Xs[r][k8 + lc];
                af[mm][1] = Xs[r + 8][k8 + lc];
                af[mm][2] = Xs[r][k8 + lc + 4];
                af[mm][3] = Xs[r + 8][k8 + lc + 4];
            }
            #pragma unroll
            for (int nn = 0; nn < 4; nn++) {
                int j = wn * 32 + nn * 8 + lr;
                bf[nn][0] = As[k8 + lc][j];
                bf[nn][1] = As[k8 + lc + 4][j];
            }
            #pragma unroll
            for (int mm = 0; mm < 2; mm++)
                #pragma unroll
                for (int nn = 0; nn < 4; nn++)
                    mma_tf32(acc[mm][nn], af[mm], bf[nn]);
        }
        __syncthreads();
    }

    // epilogue: scale by coef, write H
    #pragma unroll
    for (int mm = 0; mm < 2; mm++) {
        #pragma unroll
        for (int nn = 0; nn < 4; nn++) {
            int r = row0 + wm * 32 + mm * 16 + lr;
            int c = col0 + wn * 32 + nn * 8 + lc * 2;
            float2 v0 = make_float2(acc[mm][nn][0] * coef, acc[mm][nn][1] * coef);
            float2 v1 = make_float2(acc[mm][nn][2] * coef, acc[mm][nn][3] * coef);
            *(float2*)(g_H + (size_t)r * HCOLS + c)       = v0;
            *(float2*)(g_H + (size_t)(r + 8) * HCOLS + c) = v1;
        }
    }
}

// ---------------------------------------------------------------------------
// GEMM2: out[8192,12288]; per component out = H_comp[8192,512] @ B_comp[512,4096]
// Block tile 128x128, BK=32; BN=128 divides 4096 so each block is one component
// ---------------------------------------------------------------------------
constexpr int BN2 = 128;
constexpr int BS2 = 136;  // 136 % 32 == 8 -> conflict-free B-fragment loads

__global__ void __launch_bounds__(256, 2)
lora_gemm2(const float* __restrict__ qB,
           const float* __restrict__ kB,
           const float* __restrict__ vB,
           float* __restrict__ out)
{
    __shared__ unsigned Hs[BM][XS];
    __shared__ unsigned Bs[BK][BS2];

    const int tid  = threadIdx.x;
    const int lane = tid & 31;
    const int wid  = tid >> 5;
    const int wm   = wid & 3;   // 4 warps over M
    const int wn   = wid >> 2;  // 2 warps over N (64 cols each)
    const int lr   = lane >> 2;
    const int lc   = lane & 3;

    const int row0 = blockIdx.x * BM;
    const int col0 = blockIdx.y * BN2;       // 0..12287
    const int comp = col0 >> 12;
    const int cl   = col0 & 4095;
    const float* Bp = (comp == 0) ? qB : ((comp == 1) ? kB : vB);  // [512][4096]
    const float* Hb = g_H + (size_t)row0 * HCOLS + comp * NR;

    float acc[2][8][4];
    #pragma unroll
    for (int i = 0; i < 2; i++)
        #pragma unroll
        for (int j = 0; j < 8; j++)
            #pragma unroll
            for (int q = 0; q < 4; q++) acc[i][j][q] = 0.f;

    const int NT = NR / BK;  // 16
    for (int t = 0; t < NT; t++) {
        const int kt = t * BK;
        // H tile [128 rows][32 k]
        #pragma unroll
        for (int i = 0; i < 4; i++) {
            int lin = tid + 256 * i;
            int r = lin >> 3, c4 = (lin & 7) << 2;
            float4 v = *(const float4*)(Hb + (size_t)r * HCOLS + kt + c4);
            Hs[r][c4 + 0] = f2tf32(v.x);
            Hs[r][c4 + 1] = f2tf32(v.y);
            Hs[r][c4 + 2] = f2tf32(v.z);
            Hs[r][c4 + 3] = f2tf32(v.w);
        }
        // B tile [32 k][128 n]
        #pragma unroll
        for (int i = 0; i < 4; i++) {
            int lin = tid + 256 * i;
            int k = lin >> 5, c4 = (lin & 31) << 2;
            float4 v = *(const float4*)(Bp + (size_t)(kt + k) * DOUT + cl + c4);
            Bs[k][c4 + 0] = f2tf32(v.x);
            Bs[k][c4 + 1] = f2tf32(v.y);
            Bs[k][c4 + 2] = f2tf32(v.z);
            Bs[k][c4 + 3] = f2tf32(v.w);
        }
        __syncthreads();

        #pragma unroll
        for (int ks = 0; ks < 4; ks++) {
            const int k8 = ks * 8;
            unsigned af[2][4], bf[8][2];
            #pragma unroll
            for (int mm = 0; mm < 2; mm++) {
                int r = wm * 32 + mm * 16 + lr;
                af[mm][0] = Hs[r][k8 + lc];
                af[mm][1] = Hs[r + 8][k8 + lc];
                af[mm][2] = Hs[r][k8 + lc + 4];
                af[mm][3] = Hs[r + 8][k8 + lc + 4];
            }
            #pragma unroll
            for (int nn = 0; nn < 8; nn++) {
                int j = wn * 64 + nn * 8 + lr;
                bf[nn][0] = Bs[k8 + lc][j];
                bf[nn][1] = Bs[k8 + lc + 4][j];
            }
            #pragma unroll
            for (int mm = 0; mm < 2; mm++)
                #pragma unroll
                for (int nn = 0; nn < 8; nn++)
                    mma_tf32(acc[mm][nn], af[mm], bf[nn]);
        }
        __syncthreads();
    }

    // epilogue: write final output (covers all 8192x12288 exactly)
    #pragma unroll
    for (int mm = 0; mm < 2; mm++) {
        #pragma unroll
        for (int nn = 0; nn < 8; nn++) {
            int r = row0 + wm * 32 + mm * 16 + lr;
            int c = col0 + wn * 64 + nn * 8 + lc * 2;
            float2 v0 = make_float2(acc[mm][nn][0], acc[mm][nn][1]);
            float2 v1 = make_float2(acc[mm][nn][2], acc[mm][nn][3]);
            *(float2*)(out + (size_t)r * OUTCOLS + c)       = v0;
            *(float2*)(out + (size_t)(r + 8) * OUTCOLS + c) = v1;
        }
    }
}

extern "C" void kernel_launch(void* const* d_in, const int* in_sizes, int n_in,
                              void* d_out, int out_size) {
    // metadata order: x, output(zeros, unused), masks, scaling, qA, qB, kA, kB, vA, vB
    const float* x       = (const float*)d_in[0];
    const float* masks   = (const float*)d_in[2];
    const float* scaling = (const float*)d_in[3];
    const float* qA      = (const float*)d_in[4];
    const float* qB      = (const float*)d_in[5];
    const float* kA      = (const float*)d_in[6];
    const float* kB      = (const float*)d_in[7];
    const float* vA      = (const float*)d_in[8];
    const float* vB      = (const float*)d_in[9];
    float* out = (float*)d_out;

    lora_gemm1<<<dim3(MTOT / BM, HCOLS / BN1), 256>>>(x, qA, kA, vA, masks, scaling);
    lora_gemm2<<<dim3(MTOT / BM, OUTCOLS / BN2), 256>>>(qB, kB, vB, out);
}

// round 3
// speedup vs baseline: 2.3540x; 2.3540x over previous
#include <cuda_runtime.h>
#include <cuda_fp16.h>
#include <cstdint>

#define DIN     4096
#define RANK    64
#define MTOT    8192
#define NR      512
#define HCOLS   1536
#define DOUT    4096
#define OUTCOLS 12288

// fp16 staging buffers (device globals; no runtime allocation allowed)
__device__ __align__(16) __half g_Xh[(size_t)MTOT * DIN];    // 64 MB
__device__ __align__(16) __half g_Ah[(size_t)HCOLS * DIN];   // 12.5 MB  [j][k]
__device__ __align__(16) __half g_Bh[(size_t)3 * DOUT * NR]; // 12.5 MB  [comp][n][k]
__device__ __align__(16) __half g_Hh[(size_t)MTOT * HCOLS];  // 25 MB    [m][j]

// ---------------------------------------------------------------------------
// PTX helpers
// ---------------------------------------------------------------------------
__device__ __forceinline__ uint32_t s2u(const void* p) {
    uint32_t a;
    asm("{ .reg .u64 t; cvta.to.shared.u64 t, %1; cvt.u32.u64 %0, t; }" : "=r"(a) : "l"(p));
    return a;
}
__device__ __forceinline__ void cpasync16(uint32_t dst, const void* src) {
    asm volatile("cp.async.cg.shared.global [%0], [%1], 16;" :: "r"(dst), "l"(src) : "memory");
}
#define CP_COMMIT()  asm volatile("cp.async.commit_group;" ::: "memory")
#define CP_WAIT(n)   asm volatile("cp.async.wait_group %0;" :: "n"(n) : "memory")

__device__ __forceinline__ void ldsm4(uint32_t* r, uint32_t a) {
    asm volatile("ldmatrix.sync.aligned.m8n8.x4.shared.b16 {%0,%1,%2,%3}, [%4];"
                 : "=r"(r[0]), "=r"(r[1]), "=r"(r[2]), "=r"(r[3]) : "r"(a));
}
__device__ __forceinline__ void mma16816(float* c, const uint32_t* a, const uint32_t* b) {
    asm volatile(
        "mma.sync.aligned.m16n8k16.row.col.f32.f16.f16.f32 "
        "{%0,%1,%2,%3},{%4,%5,%6,%7},{%8,%9},{%0,%1,%2,%3};"
        : "+f"(c[0]), "+f"(c[1]), "+f"(c[2]), "+f"(c[3])
        : "r"(a[0]), "r"(a[1]), "r"(a[2]), "r"(a[3]), "r"(b[0]), "r"(b[1]));
}
// smem tile: row = BK(64) halves = 128B = 8 chunks of 16B; swizzle chunk ^= row&7
__device__ __forceinline__ uint32_t swz(int row, int chunk) {
    return (uint32_t)(row * 8 + (chunk ^ (row & 7))) * 16u;
}

// ---------------------------------------------------------------------------
// Prep kernels: fp32 -> fp16 convert / transpose
// ---------------------------------------------------------------------------
__global__ void convx_k(const float* __restrict__ x) {
    size_t i = ((size_t)blockIdx.x * 512 + threadIdx.x) * 8;
    float4 a = *(const float4*)(x + i);
    float4 b = *(const float4*)(x + i + 4);
    __half2 h[4];
    h[0] = __floats2half2_rn(a.x, a.y);
    h[1] = __floats2half2_rn(a.z, a.w);
    h[2] = __floats2half2_rn(b.x, b.y);
    h[3] = __floats2half2_rn(b.z, b.w);
    *(uint4*)(g_Xh + i) = *(uint4*)h;
}

__global__ void transA_k(const float* __restrict__ qA, const float* __restrict__ kA,
                         const float* __restrict__ vA) {
    __shared__ float t[32][33];
    int z = blockIdx.z, comp = z >> 3, n = z & 7;
    const float* src = (comp == 0 ? qA : (comp == 1 ? kA : vA)) + (size_t)n * DIN * RANK;
    int i0 = blockIdx.x * 32, r0 = blockIdx.y * 32;
    int tx = threadIdx.x, ty = threadIdx.y;
    #pragma unroll
    for (int q = 0; q < 4; q++)
        t[ty + q * 8][tx] = src[(size_t)(i0 + ty + q * 8) * RANK + r0 + tx];
    __syncthreads();
    size_t jb = (size_t)(comp * 512 + n * 64 + r0);
    #pragma unroll
    for (int q = 0; q < 4; q++)
        g_Ah[(jb + ty + q * 8) * DIN + i0 + tx] = __float2half_rn(t[tx][ty + q * 8]);
}

__global__ void transB_k(const float* __restrict__ qB, const float* __restrict__ kB,
                         const float* __restrict__ vB) {
    __shared__ float t[32][33];
    int comp = blockIdx.z;
    const float* src = (comp == 0 ? qB : (comp == 1 ? kB : vB));  // [512][4096]
    int k0 = blockIdx.x * 32, n0 = blockIdx.y * 32;
    int tx = threadIdx.x, ty = threadIdx.y;
    #pragma unroll
    for (int q = 0; q < 4; q++)
        t[ty + q * 8][tx] = src[(size_t)(k0 + ty + q * 8) * DOUT + n0 + tx];
    __syncthreads();
    __half* dst = g_Bh + (size_t)comp * DOUT * NR;
    #pragma unroll
    for (int q = 0; q < 4; q++)
        dst[(size_t)(n0 + ty + q * 8) * NR + k0 + tx] = __float2half_rn(t[tx][ty + q * 8]);
}

// ---------------------------------------------------------------------------
// GEMM core: C[128m x 256n] += A[128 x K] * B[256 x K]^T   (both K-major fp16)
// 512 threads = 16 warps (4m x 4n), warp tile m32 x n64, BK=64, 3-stage cp.async
// ---------------------------------------------------------------------------
constexpr int STAGE_B = 48 * 1024;   // 16KB A + 32KB B per stage
constexpr int BSTAGES = 3;

template <int NT>
__device__ __forceinline__ void gemm_core(const __half* Ag, int lda,   // lda in halves
                                          const __half* Bg, int ldb,
                                          char* sm, float acc[2][8][4]) {
    const int tid  = threadIdx.x;
    const int lane = tid & 31;
    const int wid  = tid >> 5;
    const int wm   = wid >> 2;   // 0..3  (m offset 32)
    const int wn   = wid & 3;    // 0..3  (n offset 64)
    uint32_t smu = s2u(sm);

    auto issue = [&](int t) {
        const int slot = t % BSTAGES;
        const uint32_t sa = smu + slot * STAGE_B;
        const uint32_t sb = sa + 16384;
        const char* agb = (const char*)Ag + (size_t)t * 128;   // t*64 halves
        const char* bgb = (const char*)Bg + (size_t)t * 128;
        #pragma unroll
        for (int i = 0; i < 2; i++) {                 // A: 1024 chunks / 512 thr
            int lin = tid + 512 * i;
            int row = lin >> 3, c = lin & 7;
            cpasync16(sa + swz(row, c), agb + (size_t)row * lda * 2 + c * 16);
        }
        #pragma unroll
        for (int i = 0; i < 4; i++) {                 // B: 2048 chunks
            int lin = tid + 512 * i;
            int row = lin >> 3, c = lin & 7;
            cpasync16(sb + swz(row, c), bgb + (size_t)row * ldb * 2 + c * 16);
        }
        CP_COMMIT();
    };

    issue(0);
    if (NT > 1) issue(1);

    for (int t = 0; t < NT; t++) {
        if (t == NT - 1) { CP_WAIT(0); } else { CP_WAIT(1); }
        __syncthreads();
        if (t + 2 < NT) issue(t + 2);

        const int slot = t % BSTAGES;
        const uint32_t sa = smu + slot * STAGE_B;
        const uint32_t sb = sa + 16384;
        #pragma unroll
        for (int ks = 0; ks < 4; ks++) {
            uint32_t af[2][4], bf[4][4];
            #pragma unroll
            for (int mt = 0; mt < 2; mt++) {
                int row = wm * 32 + mt * 16 + (lane & 15);
                ldsm4(af[mt], sa + swz(row, ks * 2 + (lane >> 4)));
            }
            #pragma unroll
            for (int ng = 0; ng < 4; ng++) {
                int row = wn * 64 + ng * 16 + (lane & 7) + ((lane >> 4) << 3);
                ldsm4(bf[ng], sb + swz(row, ks * 2 + ((lane >> 3) & 1)));
            }
            #pragma unroll
            for (int mt = 0; mt < 2; mt++)
                #pragma unroll
                for (int ng = 0; ng < 4; ng++) {
                    mma16816(acc[mt][ng * 2 + 0], af[mt], &bf[ng][0]);
                    mma16816(acc[mt][ng * 2 + 1], af[mt], &bf[ng][2]);
                }
        }
    }
}

// ---------------------------------------------------------------------------
// GEMM1: H[8192,1536] = Xh @ Ah^T, epilogue *= coef (scalar per 64-col block)
// ---------------------------------------------------------------------------
__global__ void __launch_bounds__(512, 1)
tc_gemm1(const float* __restrict__ masks, const float* __restrict__ scaling) {
    extern __shared__ __align__(16) char sm[];
    const int row0 = blockIdx.y * 128;
    const int col0 = blockIdx.x * 256;

    float acc[2][8][4];
    #pragma unroll
    for (int i = 0; i < 2; i++)
        #pragma unroll
        for (int j = 0; j < 8; j++)
            #pragma unroll
            for (int q = 0; q < 4; q++) acc[i][j][q] = 0.f;

    gemm_core<DIN / 64>(g_Xh + (size_t)row0 * DIN, DIN,
                        g_Ah + (size_t)col0 * DIN, DIN, sm, acc);

    const int tid = threadIdx.x, lane = tid & 31, wid = tid >> 5;
    const int wm = wid >> 2, wn = wid & 3;
    const int nad = ((col0 + wn * 64) >> 6) & 7;
    const int b   = row0 >> 11;
    const float coef = scaling[nad] * masks[nad * 4 + b];

    #pragma unroll
    for (int mt = 0; mt < 2; mt++) {
        #pragma unroll
        for (int ni = 0; ni < 8; ni++) {
            int r = row0 + wm * 32 + mt * 16 + (lane >> 2);
            int c = col0 + wn * 64 + ni * 8 + 2 * (lane & 3);
            *(__half2*)(g_Hh + (size_t)r * HCOLS + c) =
                __floats2half2_rn(acc[mt][ni][0] * coef, acc[mt][ni][1] * coef);
            *(__half2*)(g_Hh + (size_t)(r + 8) * HCOLS + c) =
                __floats2half2_rn(acc[mt][ni][2] * coef, acc[mt][ni][3] * coef);
        }
    }
}

// ---------------------------------------------------------------------------
// GEMM2: out[8192,12288]; per comp: out = Hh_comp @ Bh_comp^T
// ---------------------------------------------------------------------------
__global__ void __launch_bounds__(512, 1)
tc_gemm2(float* __restrict__ out) {
    extern __shared__ __align__(16) char sm[];
    const int row0 = blockIdx.y * 128;
    const int col0 = blockIdx.x * 256;
    const int comp = col0 >> 12;
    const int cl   = col0 & 4095;

    float acc[2][8][4];
    #pragma unroll
    for (int i = 0; i < 2; i++)
        #pragma unroll
        for (int j = 0; j < 8; j++)
            #pragma unroll
            for (int q = 0; q < 4; q++) acc[i][j][q] = 0.f;

    gemm_core<NR / 64>(g_Hh + (size_t)row0 * HCOLS + comp * NR, HCOLS,
                       g_Bh + (size_t)comp * DOUT * NR + (size_t)cl * NR, NR, sm, acc);

    const int tid = threadIdx.x, lane = tid & 31, wid = tid >> 5;
    const int wm = wid >> 2, wn = wid & 3;

    #pragma unroll
    for (int mt = 0; mt < 2; mt++) {
        #pragma unroll
        for (int ni = 0; ni < 8; ni++) {
            int r = row0 + wm * 32 + mt * 16 + (lane >> 2);
            int c = col0 + wn * 64 + ni * 8 + 2 * (lane & 3);
            *(float2*)(out + (size_t)r * OUTCOLS + c) =
                make_float2(acc[mt][ni][0], acc[mt][ni][1]);
            *(float2*)(out + (size_t)(r + 8) * OUTCOLS + c) =
                make_float2(acc[mt][ni][2], acc[mt][ni][3]);
        }
    }
}

// ---------------------------------------------------------------------------
extern "C" void kernel_launch(void* const* d_in, const int* in_sizes, int n_in,
                              void* d_out, int out_size) {
    const float* x       = (const float*)d_in[0];
    const float* masks   = (const float*)d_in[2];
    const float* scaling = (const float*)d_in[3];
    const float* qA      = (const float*)d_in[4];
    const float* qB      = (const float*)d_in[5];
    const float* kA      = (const float*)d_in[6];
    const float* kB      = (const float*)d_in[7];
    const float* vA      = (const float*)d_in[8];
    const float* vB      = (const float*)d_in[9];
    float* out = (float*)d_out;

    const int SMEM = BSTAGES * STAGE_B;   // 147456
    cudaFuncSetAttribute(tc_gemm1, cudaFuncAttributeMaxDynamicSharedMemorySize, SMEM);
    cudaFuncSetAttribute(tc_gemm2, cudaFuncAttributeMaxDynamicSharedMemorySize, SMEM);

    convx_k<<<(MTOT * DIN) / (512 * 8), 512>>>(x);
    transA_k<<<dim3(DIN / 32, RANK / 32, 24), dim3(32, 8)>>>(qA, kA, vA);
    transB_k<<<dim3(NR / 32, DOUT / 32, 3), dim3(32, 8)>>>(qB, kB, vB);
    // grid.x = columns (fastest) so same-row blocks are adjacent -> L2 reuse of A rows
    tc_gemm1<<<dim3(HCOLS / 256, MTOT / 128), 512, SMEM>>>(masks, scaling);
    tc_gemm2<<<dim3(OUTCOLS / 256, MTOT / 128), 512, SMEM>>>(out);
}

// round 4
// speedup vs baseline: 2.3584x; 1.0019x over previous
#include <cuda_runtime.h>
#include <cuda_fp16.h>
#include <cstdint>

#define DIN     4096
#define RANK    64
#define MTOT    8192
#define NR      512
#define HCOLS   1536
#define DOUT    4096
#define OUTCOLS 12288

// fp16 staging buffers (device globals; no runtime allocation allowed)
__device__ __align__(16) __half g_Xh[(size_t)MTOT * DIN];    // 64 MB
__device__ __align__(16) __half g_Ah[(size_t)HCOLS * DIN];   // 12.5 MB  [j][k]
__device__ __align__(16) __half g_Bh[(size_t)3 * DOUT * NR]; // 12.5 MB  [comp][n][k]
__device__ __align__(16) __half g_Hh[(size_t)MTOT * HCOLS];  // 25 MB    [m][j]

// ---------------------------------------------------------------------------
// PTX helpers
// ---------------------------------------------------------------------------
__device__ __forceinline__ uint32_t s2u(const void* p) {
    uint32_t a;
    asm("{ .reg .u64 t; cvta.to.shared.u64 t, %1; cvt.u32.u64 %0, t; }" : "=r"(a) : "l"(p));
    return a;
}
__device__ __forceinline__ void cpasync16(uint32_t dst, const void* src) {
    asm volatile("cp.async.cg.shared.global [%0], [%1], 16;" :: "r"(dst), "l"(src) : "memory");
}
#define CP_COMMIT()  asm volatile("cp.async.commit_group;" ::: "memory")
#define CP_WAIT(n)   asm volatile("cp.async.wait_group %0;" :: "n"(n) : "memory")

__device__ __forceinline__ void ldsm4(uint32_t* r, uint32_t a) {
    asm volatile("ldmatrix.sync.aligned.m8n8.x4.shared.b16 {%0,%1,%2,%3}, [%4];"
                 : "=r"(r[0]), "=r"(r[1]), "=r"(r[2]), "=r"(r[3]) : "r"(a));
}
__device__ __forceinline__ void mma16816(float* c, const uint32_t* a, const uint32_t* b) {
    asm volatile(
        "mma.sync.aligned.m16n8k16.row.col.f32.f16.f16.f32 "
        "{%0,%1,%2,%3},{%4,%5,%6,%7},{%8,%9},{%0,%1,%2,%3};"
        : "+f"(c[0]), "+f"(c[1]), "+f"(c[2]), "+f"(c[3])
        : "r"(a[0]), "r"(a[1]), "r"(a[2]), "r"(a[3]), "r"(b[0]), "r"(b[1]));
}
// smem tile: row = BK(64) halves = 128B = 8 chunks of 16B; swizzle chunk ^= row&7
__device__ __forceinline__ uint32_t swz(int row, int chunk) {
    return (uint32_t)(row * 8 + (chunk ^ (row & 7))) * 16u;
}

// ---------------------------------------------------------------------------
// Prep kernels: fp32 -> fp16 convert / transpose
// ---------------------------------------------------------------------------
__global__ void convx_k(const float* __restrict__ x) {
    size_t i = ((size_t)blockIdx.x * 512 + threadIdx.x) * 8;
    float4 a = *(const float4*)(x + i);
    float4 b = *(const float4*)(x + i + 4);
    __half2 h[4];
    h[0] = __floats2half2_rn(a.x, a.y);
    h[1] = __floats2half2_rn(a.z, a.w);
    h[2] = __floats2half2_rn(b.x, b.y);
    h[3] = __floats2half2_rn(b.z, b.w);
    *(uint4*)(g_Xh + i) = *(uint4*)h;
}

__global__ void transA_k(const float* __restrict__ qA, const float* __restrict__ kA,
                         const float* __restrict__ vA) {
    __shared__ float t[32][33];
    int z = blockIdx.z, comp = z >> 3, n = z & 7;
    const float* src = (comp == 0 ? qA : (comp == 1 ? kA : vA)) + (size_t)n * DIN * RANK;
    int i0 = blockIdx.x * 32, r0 = blockIdx.y * 32;
    int tx = threadIdx.x, ty = threadIdx.y;
    #pragma unroll
    for (int q = 0; q < 4; q++)
        t[ty + q * 8][tx] = src[(size_t)(i0 + ty + q * 8) * RANK + r0 + tx];
    __syncthreads();
    size_t jb = (size_t)(comp * 512 + n * 64 + r0);
    #pragma unroll
    for (int q = 0; q < 4; q++)
        g_Ah[(jb + ty + q * 8) * DIN + i0 + tx] = __float2half_rn(t[tx][ty + q * 8]);
}

__global__ void transB_k(const float* __restrict__ qB, const float* __restrict__ kB,
                         const float* __restrict__ vB) {
    __shared__ float t[32][33];
    int comp = blockIdx.z;
    const float* src = (comp == 0 ? qB : (comp == 1 ? kB : vB));  // [512][4096]
    int k0 = blockIdx.x * 32, n0 = blockIdx.y * 32;
    int tx = threadIdx.x, ty = threadIdx.y;
    #pragma unroll
    for (int q = 0; q < 4; q++)
        t[ty + q * 8][tx] = src[(size_t)(k0 + ty + q * 8) * DOUT + n0 + tx];
    __syncthreads();
    __half* dst = g_Bh + (size_t)comp * DOUT * NR;
    #pragma unroll
    for (int q = 0; q < 4; q++)
        dst[(size_t)(n0 + ty + q * 8) * NR + k0 + tx] = __float2half_rn(t[tx][ty + q * 8]);
}

// ---------------------------------------------------------------------------
// GEMM core: C[128m x 256n] += A[128 x K] * B[256 x K]^T   (both K-major fp16)
// 512 threads = 16 warps (4m x 4n), warp tile m32 x n64, BK=64, 3-stage cp.async
// Per-warp k-subtile phase skew: warps start at different ks so LDSM of some
// warps overlaps HMMA of others instead of phase-locking after the barrier.
// ---------------------------------------------------------------------------
constexpr int STAGE_B = 48 * 1024;   // 16KB A + 32KB B per stage
constexpr int BSTAGES = 3;

template <int NT>
__device__ __forceinline__ void gemm_core(const __half* Ag, int lda,   // lda in halves
                                          const __half* Bg, int ldb,
                                          char* sm, float acc[2][8][4]) {
    const int tid  = threadIdx.x;
    const int lane = tid & 31;
    const int wid  = tid >> 5;
    const int wm   = wid >> 2;   // 0..3  (m offset 32)
    const int wn   = wid & 3;    // 0..3  (n offset 64)
    uint32_t smu = s2u(sm);

    auto issue = [&](int t) {
        const int slot = t % BSTAGES;
        const uint32_t sa = smu + slot * STAGE_B;
        const uint32_t sb = sa + 16384;
        const char* agb = (const char*)Ag + (size_t)t * 128;   // t*64 halves
        const char* bgb = (const char*)Bg + (size_t)t * 128;
        #pragma unroll
        for (int i = 0; i < 2; i++) {                 // A: 1024 chunks / 512 thr
            int lin = tid + 512 * i;
            int row = lin >> 3, c = lin & 7;
            cpasync16(sa + swz(row, c), agb + (size_t)row * lda * 2 + c * 16);
        }
        #pragma unroll
        for (int i = 0; i < 4; i++) {                 // B: 2048 chunks
            int lin = tid + 512 * i;
            int row = lin >> 3, c = lin & 7;
            cpasync16(sb + swz(row, c), bgb + (size_t)row * ldb * 2 + c * 16);
        }
        CP_COMMIT();
    };

    issue(0);
    if (NT > 1) issue(1);

    #pragma unroll 1
    for (int t = 0; t < NT; t++) {
        if (t == NT - 1) { CP_WAIT(0); } else { CP_WAIT(1); }
        __syncthreads();
        if (t + 2 < NT) issue(t + 2);

        const int slot = t % BSTAGES;
        const uint32_t sa = smu + slot * STAGE_B;
        const uint32_t sb = sa + 16384;
        #pragma unroll
        for (int kss = 0; kss < 4; kss++) {
            const int ks = (kss + wid) & 3;   // phase skew per warp
            uint32_t af[2][4], bf[4][4];
            #pragma unroll
            for (int mt = 0; mt < 2; mt++) {
                int row = wm * 32 + mt * 16 + (lane & 15);
                ldsm4(af[mt], sa + swz(row, ks * 2 + (lane >> 4)));
            }
            #pragma unroll
            for (int ng = 0; ng < 4; ng++) {
                int row = wn * 64 + ng * 16 + (lane & 7) + ((lane >> 4) << 3);
                ldsm4(bf[ng], sb + swz(row, ks * 2 + ((lane >> 3) & 1)));
            }
            #pragma unroll
            for (int mt = 0; mt < 2; mt++)
                #pragma unroll
                for (int ng = 0; ng < 4; ng++) {
                    mma16816(acc[mt][ng * 2 + 0], af[mt], &bf[ng][0]);
                    mma16816(acc[mt][ng * 2 + 1], af[mt], &bf[ng][2]);
                }
        }
    }
}

// ---------------------------------------------------------------------------
// GEMM1: H[8192,1536] = Xh @ Ah^T, epilogue *= coef (scalar per 64-col block)
// ---------------------------------------------------------------------------
__global__ void __launch_bounds__(512, 1)
tc_gemm1(const float* __restrict__ masks, const float* __restrict__ scaling) {
    extern __shared__ __align__(16) char sm[];
    const int row0 = blockIdx.y * 128;
    const int col0 = blockIdx.x * 256;

    float acc[2][8][4];
    #pragma unroll
    for (int i = 0; i < 2; i++)
        #pragma unroll
        for (int j = 0; j < 8; j++)
            #pragma unroll
            for (int q = 0; q < 4; q++) acc[i][j][q] = 0.f;

    gemm_core<DIN / 64>(g_Xh + (size_t)row0 * DIN, DIN,
                        g_Ah + (size_t)col0 * DIN, DIN, sm, acc);

    const int tid = threadIdx.x, lane = tid & 31, wid = tid >> 5;
    const int wm = wid >> 2, wn = wid & 3;
    const int nad = ((col0 + wn * 64) >> 6) & 7;
    const int b   = row0 >> 11;
    const float coef = scaling[nad] * masks[nad * 4 + b];

    #pragma unroll
    for (int mt = 0; mt < 2; mt++) {
        #pragma unroll
        for (int ni = 0; ni < 8; ni++) {
            int r = row0 + wm * 32 + mt * 16 + (lane >> 2);
            int c = col0 + wn * 64 + ni * 8 + 2 * (lane & 3);
            *(__half2*)(g_Hh + (size_t)r * HCOLS + c) =
                __floats2half2_rn(acc[mt][ni][0] * coef, acc[mt][ni][1] * coef);
            *(__half2*)(g_Hh + (size_t)(r + 8) * HCOLS + c) =
                __floats2half2_rn(acc[mt][ni][2] * coef, acc[mt][ni][3] * coef);
        }
    }
}

// ---------------------------------------------------------------------------
// GEMM2: out[8192,12288]; per comp: out = Hh_comp @ Bh_comp^T
// ---------------------------------------------------------------------------
__global__ void __launch_bounds__(512, 1)
tc_gemm2(float* __restrict__ out) {
    extern __shared__ __align__(16) char sm[];
    const int row0 = blockIdx.y * 128;
    const int col0 = blockIdx.x * 256;
    const int comp = col0 >> 12;
    const int cl   = col0 & 4095;

    float acc[2][8][4];
    #pragma unroll
    for (int i = 0; i < 2; i++)
        #pragma unroll
        for (int j = 0; j < 8; j++)
            #pragma unroll
            for (int q = 0; q < 4; q++) acc[i][j][q] = 0.f;

    gemm_core<NR / 64>(g_Hh + (size_t)row0 * HCOLS + comp * NR, HCOLS,
                       g_Bh + (size_t)comp * DOUT * NR + (size_t)cl * NR, NR, sm, acc);

    const int tid = threadIdx.x, lane = tid & 31, wid = tid >> 5;
    const int wm = wid >> 2, wn = wid & 3;

    #pragma unroll
    for (int mt = 0; mt < 2; mt++) {
        #pragma unroll
        for (int ni = 0; ni < 8; ni++) {
            int r = row0 + wm * 32 + mt * 16 + (lane >> 2);
            int c = col0 + wn * 64 + ni * 8 + 2 * (lane & 3);
            *(float2*)(out + (size_t)r * OUTCOLS + c) =
                make_float2(acc[mt][ni][0], acc[mt][ni][1]);
            *(float2*)(out + (size_t)(r + 8) * OUTCOLS + c) =
                make_float2(acc[mt][ni][2], acc[mt][ni][3]);
        }
    }
}

// ---------------------------------------------------------------------------
extern "C" void kernel_launch(void* const* d_in, const int* in_sizes, int n_in,
                              void* d_out, int out_size) {
    const float* x       = (const float*)d_in[0];
    const float* masks   = (const float*)d_in[2];
    const float* scaling = (const float*)d_in[3];
    const float* qA      = (const float*)d_in[4];
    const float* qB      = (const float*)d_in[5];
    const float* kA      = (const float*)d_in[6];
    const float* kB      = (const float*)d_in[7];
    const float* vA      = (const float*)d_in[8];
    const float* vB      = (const float*)d_in[9];
    float* out = (float*)d_out;

    const int SMEM = BSTAGES * STAGE_B;   // 147456
    cudaFuncSetAttribute(tc_gemm1, cudaFuncAttributeMaxDynamicSharedMemorySize, SMEM);
    cudaFuncSetAttribute(tc_gemm2, cudaFuncAttributeMaxDynamicSharedMemorySize, SMEM);

    convx_k<<<(MTOT * DIN) / (512 * 8), 512>>>(x);
    transA_k<<<dim3(DIN / 32, RANK / 32, 24), dim3(32, 8)>>>(qA, kA, vA);
    transB_k<<<dim3(NR / 32, DOUT / 32, 3), dim3(32, 8)>>>(qB, kB, vB);
    // grid.x = columns (fastest) so same-row blocks are adjacent -> L2 reuse of A rows
    tc_gemm1<<<dim3(HCOLS / 256, MTOT / 128), 512, SMEM>>>(masks, scaling);
    tc_gemm2<<<dim3(OUTCOLS / 256, MTOT / 128), 512, SMEM>>>(out);
}

// round 5
// speedup vs baseline: 2.4567x; 1.0417x over previous
#include <cuda_runtime.h>
#include <cuda_fp16.h>
#include <cstdint>

#define DIN     4096
#define RANK    64
#define MTOT    8192
#define NR      512
#define HCOLS   1536
#define DOUT    4096
#define OUTCOLS 12288

// fp16 staging buffers (device globals; no runtime allocation allowed)
__device__ __align__(16) __half g_Xh[(size_t)MTOT * DIN];    // 64 MB
__device__ __align__(16) __half g_Ah[(size_t)HCOLS * DIN];   // 12.5 MB  [j][k]
__device__ __align__(16) __half g_Bh[(size_t)3 * DOUT * NR]; // 12.5 MB  [comp][n][k]
__device__ __align__(16) __half g_Hh[(size_t)MTOT * HCOLS];  // 25 MB    [m][j]

// ---------------------------------------------------------------------------
// PTX helpers
// ---------------------------------------------------------------------------
__device__ __forceinline__ uint32_t s2u(const void* p) {
    uint32_t a;
    asm("{ .reg .u64 t; cvta.to.shared.u64 t, %1; cvt.u32.u64 %0, t; }" : "=r"(a) : "l"(p));
    return a;
}
__device__ __forceinline__ void cpasync16(uint32_t dst, const void* src) {
    asm volatile("cp.async.cg.shared.global [%0], [%1], 16;" :: "r"(dst), "l"(src) : "memory");
}
#define CP_COMMIT()  asm volatile("cp.async.commit_group;" ::: "memory")
#define CP_WAIT(n)   asm volatile("cp.async.wait_group %0;" :: "n"(n) : "memory")

__device__ __forceinline__ void ldsm4(uint32_t* r, uint32_t a) {
    asm volatile("ldmatrix.sync.aligned.m8n8.x4.shared.b16 {%0,%1,%2,%3}, [%4];"
                 : "=r"(r[0]), "=r"(r[1]), "=r"(r[2]), "=r"(r[3]) : "r"(a));
}
__device__ __forceinline__ void mma16816(float* c, const uint32_t* a, const uint32_t* b) {
    asm volatile(
        "mma.sync.aligned.m16n8k16.row.col.f32.f16.f16.f32 "
        "{%0,%1,%2,%3},{%4,%5,%6,%7},{%8,%9},{%0,%1,%2,%3};"
        : "+f"(c[0]), "+f"(c[1]), "+f"(c[2]), "+f"(c[3])
        : "r"(a[0]), "r"(a[1]), "r"(a[2]), "r"(a[3]), "r"(b[0]), "r"(b[1]));
}
// smem tile row = 64 halves = 128B = 8 chunks of 16B; swizzle chunk ^= row&7
__device__ __forceinline__ uint32_t swz(int row, int chunk) {
    return (uint32_t)(row * 8 + (chunk ^ (row & 7))) * 16u;
}

// ---------------------------------------------------------------------------
// Prep kernels: fp32 -> fp16 convert / transpose
// ---------------------------------------------------------------------------
__global__ void convx_k(const float* __restrict__ x) {
    size_t i = ((size_t)blockIdx.x * 512 + threadIdx.x) * 8;
    float4 a = *(const float4*)(x + i);
    float4 b = *(const float4*)(x + i + 4);
    __half2 h[4];
    h[0] = __floats2half2_rn(a.x, a.y);
    h[1] = __floats2half2_rn(a.z, a.w);
    h[2] = __floats2half2_rn(b.x, b.y);
    h[3] = __floats2half2_rn(b.z, b.w);
    *(uint4*)(g_Xh + i) = *(uint4*)h;
}

__global__ void transA_k(const float* __restrict__ qA, const float* __restrict__ kA,
                         const float* __restrict__ vA) {
    __shared__ float t[32][33];
    int z = blockIdx.z, comp = z >> 3, n = z & 7;
    const float* src = (comp == 0 ? qA : (comp == 1 ? kA : vA)) + (size_t)n * DIN * RANK;
    int i0 = blockIdx.x * 32, r0 = blockIdx.y * 32;
    int tx = threadIdx.x, ty = threadIdx.y;
    #pragma unroll
    for (int q = 0; q < 4; q++)
        t[ty + q * 8][tx] = src[(size_t)(i0 + ty + q * 8) * RANK + r0 + tx];
    __syncthreads();
    size_t jb = (size_t)(comp * 512 + n * 64 + r0);
    #pragma unroll
    for (int q = 0; q < 4; q++)
        g_Ah[(jb + ty + q * 8) * DIN + i0 + tx] = __float2half_rn(t[tx][ty + q * 8]);
}

__global__ void transB_k(const float* __restrict__ qB, const float* __restrict__ kB,
                         const float* __restrict__ vB) {
    __shared__ float t[32][33];
    int comp = blockIdx.z;
    const float* src = (comp == 0 ? qB : (comp == 1 ? kB : vB));  // [512][4096]
    int k0 = blockIdx.x * 32, n0 = blockIdx.y * 32;
    int tx = threadIdx.x, ty = threadIdx.y;
    #pragma unroll
    for (int q = 0; q < 4; q++)
        t[ty + q * 8][tx] = src[(size_t)(k0 + ty + q * 8) * DOUT + n0 + tx];
    __syncthreads();
    __half* dst = g_Bh + (size_t)comp * DOUT * NR;
    #pragma unroll
    for (int q = 0; q < 4; q++)
        dst[(size_t)(n0 + ty + q * 8) * NR + k0 + tx] = __float2half_rn(t[tx][ty + q * 8]);
}

// ---------------------------------------------------------------------------
// GEMM core: C[128m x 128n] += A[128 x K] * B[128 x K]^T   (both K-major fp16)
// 256 threads = 8 warps (4m x 2n), warp tile m32 x n64, BK=64, 3-stage cp.async
// 2 CTAs/SM co-resident: the other CTA hides this one's barriers/fills.
// ---------------------------------------------------------------------------
constexpr int STAGE_B = 32 * 1024;   // 16KB A + 16KB B per stage
constexpr int BSTAGES = 3;

template <int NT>
__device__ __forceinline__ void gemm_core(const __half* Ag, int lda,   // lda in halves
                                          const __half* Bg, int ldb,
                                          char* sm, float acc[2][8][4]) {
    const int tid  = threadIdx.x;
    const int lane = tid & 31;
    const int wid  = tid >> 5;
    const int wm   = wid & 3;    // 0..3  (m offset 32)
    const int wn   = wid >> 2;   // 0..1  (n offset 64)
    uint32_t smu = s2u(sm);

    auto issue = [&](int t) {
        const int slot = t % BSTAGES;
        const uint32_t sa = smu + slot * STAGE_B;
        const uint32_t sb = sa + 16384;
        const char* agb = (const char*)Ag + (size_t)t * 128;   // t*64 halves
        const char* bgb = (const char*)Bg + (size_t)t * 128;
        #pragma unroll
        for (int i = 0; i < 4; i++) {                 // A: 1024 chunks / 256 thr
            int lin = tid + 256 * i;
            int row = lin >> 3, c = lin & 7;
            cpasync16(sa + swz(row, c), agb + (size_t)row * lda * 2 + c * 16);
        }
        #pragma unroll
        for (int i = 0; i < 4; i++) {                 // B: 1024 chunks
            int lin = tid + 256 * i;
            int row = lin >> 3, c = lin & 7;
            cpasync16(sb + swz(row, c), bgb + (size_t)row * ldb * 2 + c * 16);
        }
        CP_COMMIT();
    };

    issue(0);
    if (NT > 1) issue(1);

    #pragma unroll 1
    for (int t = 0; t < NT; t++) {
        if (t == NT - 1) { CP_WAIT(0); } else { CP_WAIT(1); }
        __syncthreads();
        if (t + 2 < NT) issue(t + 2);

        const int slot = t % BSTAGES;
        const uint32_t sa = smu + slot * STAGE_B;
        const uint32_t sb = sa + 16384;
        #pragma unroll
        for (int ks = 0; ks < 4; ks++) {
            uint32_t af[2][4], bf[4][4];
            #pragma unroll
            for (int mt = 0; mt < 2; mt++) {
                int row = wm * 32 + mt * 16 + (lane & 15);
                ldsm4(af[mt], sa + swz(row, ks * 2 + (lane >> 4)));
            }
            #pragma unroll
            for (int ng = 0; ng < 4; ng++) {
                int row = wn * 64 + ng * 16 + (lane & 7) + ((lane >> 4) << 3);
                ldsm4(bf[ng], sb + swz(row, ks * 2 + ((lane >> 3) & 1)));
            }
            #pragma unroll
            for (int mt = 0; mt < 2; mt++)
                #pragma unroll
                for (int ng = 0; ng < 4; ng++) {
                    mma16816(acc[mt][ng * 2 + 0], af[mt], &bf[ng][0]);
                    mma16816(acc[mt][ng * 2 + 1], af[mt], &bf[ng][2]);
                }
        }
    }
}

// ---------------------------------------------------------------------------
// GEMM1: H[8192,1536] = Xh @ Ah^T, epilogue *= coef (scalar per 64-col block)
// Persistent CTAs loop over 12x64 = 768 tiles (col-fastest for L2 reuse).
// ---------------------------------------------------------------------------
__global__ void __launch_bounds__(256, 2)
tc_gemm1(const float* __restrict__ masks, const float* __restrict__ scaling) {
    extern __shared__ __align__(16) char sm[];
    const int tid = threadIdx.x, lane = tid & 31, wid = tid >> 5;
    const int wm = wid & 3, wn = wid >> 2;
    const int NCT = HCOLS / 128;           // 12
    const int NTILE = NCT * (MTOT / 128);  // 768

    for (int tile = blockIdx.x; tile < NTILE; tile += gridDim.x) {
        const int row0 = (tile / NCT) * 128;
        const int col0 = (tile % NCT) * 128;

        float acc[2][8][4];
        #pragma unroll
        for (int i = 0; i < 2; i++)
            #pragma unroll
            for (int j = 0; j < 8; j++)
                #pragma unroll
                for (int q = 0; q < 4; q++) acc[i][j][q] = 0.f;

        gemm_core<DIN / 64>(g_Xh + (size_t)row0 * DIN, DIN,
                            g_Ah + (size_t)col0 * DIN, DIN, sm, acc);
        __syncthreads();   // protect smem slot 0 from next tile's issue(0)

        const int nad = ((col0 + wn * 64) >> 6) & 7;
        const int b   = row0 >> 11;
        const float coef = scaling[nad] * masks[nad * 4 + b];

        #pragma unroll
        for (int mt = 0; mt < 2; mt++) {
            #pragma unroll
            for (int ni = 0; ni < 8; ni++) {
                int r = row0 + wm * 32 + mt * 16 + (lane >> 2);
                int c = col0 + wn * 64 + ni * 8 + 2 * (lane & 3);
                *(__half2*)(g_Hh + (size_t)r * HCOLS + c) =
                    __floats2half2_rn(acc[mt][ni][0] * coef, acc[mt][ni][1] * coef);
                *(__half2*)(g_Hh + (size_t)(r + 8) * HCOLS + c) =
                    __floats2half2_rn(acc[mt][ni][2] * coef, acc[mt][ni][3] * coef);
            }
        }
    }
}

// ---------------------------------------------------------------------------
// GEMM2: out[8192,12288]; per comp: out = Hh_comp @ Bh_comp^T
// Persistent CTAs loop over 96x64 = 6144 tiles.
// ---------------------------------------------------------------------------
__global__ void __launch_bounds__(256, 2)
tc_gemm2(float* __restrict__ out) {
    extern __shared__ __align__(16) char sm[];
    const int tid = threadIdx.x, lane = tid & 31, wid = tid >> 5;
    const int wm = wid & 3, wn = wid >> 2;
    const int NCT = OUTCOLS / 128;         // 96
    const int NTILE = NCT * (MTOT / 128);  // 6144

    for (int tile = blockIdx.x; tile < NTILE; tile += gridDim.x) {
        const int row0 = (tile / NCT) * 128;
        const int col0 = (tile % NCT) * 128;
        const int comp = col0 >> 12;
        const int cl   = col0 & 4095;

        float acc[2][8][4];
        #pragma unroll
        for (int i = 0; i < 2; i++)
            #pragma unroll
            for (int j = 0; j < 8; j++)
                #pragma unroll
                for (int q = 0; q < 4; q++) acc[i][j][q] = 0.f;

        gemm_core<NR / 64>(g_Hh + (size_t)row0 * HCOLS + comp * NR, HCOLS,
                           g_Bh + (size_t)comp * DOUT * NR + (size_t)cl * NR, NR, sm, acc);
        __syncthreads();

        #pragma unroll
        for (int mt = 0; mt < 2; mt++) {
            #pragma unroll
            for (int ni = 0; ni < 8; ni++) {
                int r = row0 + wm * 32 + mt * 16 + (lane >> 2);
                int c = col0 + wn * 64 + ni * 8 + 2 * (lane & 3);
                *(float2*)(out + (size_t)r * OUTCOLS + c) =
                    make_float2(acc[mt][ni][0], acc[mt][ni][1]);
                *(float2*)(out + (size_t)(r + 8) * OUTCOLS + c) =
                    make_float2(acc[mt][ni][2], acc[mt][ni][3]);
            }
        }
    }
}

// ---------------------------------------------------------------------------
extern "C" void kernel_launch(void* const* d_in, const int* in_sizes, int n_in,
                              void* d_out, int out_size) {
    const float* x       = (const float*)d_in[0];
    const float* masks   = (const float*)d_in[2];
    const float* scaling = (const float*)d_in[3];
    const float* qA      = (const float*)d_in[4];
    const float* qB      = (const float*)d_in[5];
    const float* kA      = (const float*)d_in[6];
    const float* kB      = (const float*)d_in[7];
    const float* vA      = (const float*)d_in[8];
    const float* vB      = (const float*)d_in[9];
    float* out = (float*)d_out;

    const int SMEM = BSTAGES * STAGE_B;   // 98304 per CTA -> 2 CTAs/SM
    cudaFuncSetAttribute(tc_gemm1, cudaFuncAttributeMaxDynamicSharedMemorySize, SMEM);
    cudaFuncSetAttribute(tc_gemm2, cudaFuncAttributeMaxDynamicSharedMemorySize, SMEM);

    convx_k<<<(MTOT * DIN) / (512 * 8), 512>>>(x);
    transA_k<<<dim3(DIN / 32, RANK / 32, 24), dim3(32, 8)>>>(qA, kA, vA);
    transB_k<<<dim3(NR / 32, DOUT / 32, 3), dim3(32, 8)>>>(qB, kB, vB);

    const int GRID = 2 * 148;   // persistent, 2 CTAs per SM
    tc_gemm1<<<GRID, 256, SMEM>>>(masks, scaling);
    tc_gemm2<<<GRID, 256, SMEM>>>(out);
}